// round 15
// baseline (speedup 1.0000x reference)
#include <cuda_runtime.h>
#include <math.h>

// ---------------- problem constants ----------------
#define NB 8
#define NC 32
#define NH 256
#define NW 256
#define NM 16
#define NKX 32
#define WSZ (32*32*16*16*2)

// ---------------- device scratch ----------------
__device__ float  g_bufA[NB*NC*NH*NW];
__device__ float  g_bufB[NB*NC*NH*NW];
__device__ float  g_bufC[NB*NC*NH*NW];
__device__ float2 g_Y[NB*NC*NH*NM];
__device__ float2 g_Zb[NB*NC*NKX*NM];
__device__ float2 g_G[NB*NC*NH*NM];
__device__ float2 g_G2[NB*NC*NH*NM];

// ---------------- helpers ----------------
__device__ __forceinline__ float2 ffma2(float2 a, float2 b, float2 c) {
    float2 d;
    asm("fma.rn.f32x2 %0, %1, %2, %3;"
        : "=l"(reinterpret_cast<unsigned long long&>(d))
        : "l"(reinterpret_cast<unsigned long long&>(a)),
          "l"(reinterpret_cast<unsigned long long&>(b)),
          "l"(reinterpret_cast<unsigned long long&>(c)));
    return d;
}
__device__ __forceinline__ float2 cis_m(int m) {
    float a = (float)(m & 255) * (1.0f/128.0f);
    return make_float2(cospif(a), sinpif(a));
}
// branch-free GELU (Abramowitz-Stegun erf, |err| < 1.5e-7)
__device__ __forceinline__ float gelu_f(float v) {
    float u = fabsf(v) * 0.7071067811865476f;
    float t = __frcp_rn(fmaf(0.3275911f, u, 1.0f));
    float p = t * fmaf(t, fmaf(t, fmaf(t, fmaf(t, 1.061405429f, -1.453152027f),
                                       1.421413741f), -0.284496736f), 0.254829592f);
    float e = __expf(-u * u);
    float erfv = copysignf(fmaf(-p, e, 1.0f), v);
    return 0.5f * v * (1.0f + erfv);
}

// twiddle table cs2: float2[16][130], cs2[ky*130+w] = e^{i 2pi ky w/256}, w < 128.
// Used as float2 (synthesis) and as float4 covering (w=2t, 2t+1) pairs (fwd DFT).
__device__ __forceinline__ void gen_cs2(float2* cs2, int tid) {
#pragma unroll
    for (int k = tid; k < 2048; k += 256) {
        int ky = k >> 7, w = k & 127;
        cs2[ky*130 + w] = cis_m(ky * w);
    }
}

// folded forward W-DFT: orow float2[16][258]; [p][w<128]=v(w)+v(w+128), [p][128+w]=v(w)-v(w+128)
__device__ __forceinline__ void fwd_dft(const float2* orow, const float2* cs2,
                                        float2* __restrict__ Y, int b, int h, int tid) {
    int q  = tid >> 4;
    int ky = tid & 15;
    float2 yr = make_float2(0.f, 0.f);
    float2 yi = make_float2(0.f, 0.f);
    const float4* op = (const float4*)(orow + q*258 + ((ky & 1) ? 128 : 0));
    const float4* ep = (const float4*)(cs2 + ky*130);
#pragma unroll 8
    for (int t = 0; t < 64; t++) {
        float4 o4 = op[t];
        float4 e4 = ep[t];
        yr = ffma2(make_float2(o4.x, o4.y), make_float2(e4.x,  e4.x), yr);
        yi = ffma2(make_float2(o4.x, o4.y), make_float2(-e4.y, -e4.y), yi);
        yr = ffma2(make_float2(o4.z, o4.w), make_float2(e4.z,  e4.z), yr);
        yi = ffma2(make_float2(o4.z, o4.w), make_float2(-e4.w, -e4.w), yi);
    }
    Y[((b*NC + 2*q    )*NH + h)*NM + ky] = make_float2(yr.x, yi.x);
    Y[((b*NC + 2*q + 1)*NH + h)*NM + ky] = make_float2(yr.y, yi.y);
}

// ---------------- conv + spectral-synthesis core v9 (wpt=2, 8 pairs/thread) ----------------
// thread: wl = tid&127, half = tid>>7 -> pairs half*8 .. half*8+7.
// acc[j*2+0] = (ch 2p, ch 2p+1) at w=wl; acc[j*2+1] = at w=wl+128.  p = half*8+j.
__device__ __forceinline__ void compute_vals(
        const float4* g4, const float4* cwq, const float2* cb2, const float2* cs2,
        const float* xrowf, int wl, int half, float2* acc) {
    // spectral synthesis, ky-outer: one twiddle load per ky shared by all 8 pairs
    float2 P[8], Q[8];
#pragma unroll
    for (int k = 0; k < 8; k++) {
        P[k] = make_float2(0.f, 0.f);
        Q[k] = make_float2(0.f, 0.f);
    }
#pragma unroll
    for (int ky = 0; ky < NM; ky++) {
        float2 e = cs2[ky*130 + wl];
        float2 er = make_float2(e.x, e.x), ei = make_float2(-e.y, -e.y);
        if ((ky & 1) == 0) {
#pragma unroll
            for (int j = 0; j < 8; j++) {
                float4 g = g4[(half*8 + j)*16 + ky];
                P[j] = ffma2(make_float2(g.x, g.y), er, P[j]);
                P[j] = ffma2(make_float2(g.z, g.w), ei, P[j]);
            }
        } else {
#pragma unroll
            for (int j = 0; j < 8; j++) {
                float4 g = g4[(half*8 + j)*16 + ky];
                Q[j] = ffma2(make_float2(g.x, g.y), er, Q[j]);
                Q[j] = ffma2(make_float2(g.z, g.w), ei, Q[j]);
            }
        }
    }
#pragma unroll
    for (int j = 0; j < 8; j++) {
        float2 bias = cb2[half*8 + j];
        acc[j*2+0] = make_float2(bias.x + P[j].x + Q[j].x, bias.y + P[j].y + Q[j].y);
        acc[j*2+1] = make_float2(bias.x + P[j].x - Q[j].x, bias.y + P[j].y - Q[j].y);
    }
    // 1x1 conv adds on top (x scalar per (c, w), weights broadcast)
#pragma unroll 4
    for (int c = 0; c < NC; c++) {
        float xa = xrowf[c*260 + wl];
        float xb = xrowf[c*260 + 128 + wl];
        float2 xa2 = make_float2(xa, xa), xb2 = make_float2(xb, xb);
#pragma unroll
        for (int j2 = 0; j2 < 4; j2++) {
            float4 w4 = cwq[c*8 + half*4 + j2];
            float2 wA = make_float2(w4.x, w4.y);   // pair 2j2
            float2 wB = make_float2(w4.z, w4.w);   // pair 2j2+1
            acc[(2*j2  )*2+0] = ffma2(xa2, wA, acc[(2*j2  )*2+0]);
            acc[(2*j2  )*2+1] = ffma2(xb2, wA, acc[(2*j2  )*2+1]);
            acc[(2*j2+1)*2+0] = ffma2(xa2, wB, acc[(2*j2+1)*2+0]);
            acc[(2*j2+1)*2+1] = ffma2(xb2, wB, acc[(2*j2+1)*2+1]);
        }
    }
}

// shared prologue staging (layer kernels); xrowf stride 260
__device__ __forceinline__ void stage_layer(
        float4* g4, float4* cwq, float2* cb2, float* xrowf,
        const float* xin, const float2* G, const float* cw, const float* cb,
        int b, int h, int tid) {
    for (int c = 0; c < NC; c++) xrowf[c*260 + tid] = xin[((b*NC + c)*NH + h)*NW + tid];
    {
        int c = tid >> 3, p2 = tid & 7;
        cwq[tid] = make_float4(cw[(4*p2+0)*32+c], cw[(4*p2+1)*32+c],
                               cw[(4*p2+2)*32+c], cw[(4*p2+3)*32+c]);
    }
    if (tid < 16) cb2[tid] = make_float2(cb[2*tid], cb[2*tid+1]);
    {
        int p = tid >> 4, ky = tid & 15;
        float2 ga = G[((b*NC + 2*p    )*NH + h)*NM + ky];
        float2 gb = G[((b*NC + 2*p + 1)*NH + h)*NM + ky];
        g4[p*16 + ky] = make_float4(ga.x, gb.x, ga.y, gb.y);
    }
}

// ---------------- lift ----------------
// smem: cs2[0,16640) | orow[16640,49664) | w0s[49664,51200) | b0s[51200,51328) | xstage[51328,61568)
static const int LIFT_SM = 61568;
__global__ void __launch_bounds__(256) lift_kernel(
        const float* __restrict__ x, const float* __restrict__ w0,
        const float* __restrict__ b0, float* __restrict__ out, float2* __restrict__ Y) {
    extern __shared__ unsigned char sm[];
    float2* cs2  = (float2*)sm;
    float2* orow = (float2*)(sm + 16640);
    float*  w0s  = (float*)(sm + 49664);
    float*  b0s  = (float*)(sm + 51200);
    float*  xst  = (float*)(sm + 51328);
    float*  orowf = (float*)orow;

    int b = blockIdx.x >> 8, h = blockIdx.x & 255, tid = threadIdx.x;

    gen_cs2(cs2, tid);
    for (int k = tid; k < 384; k += 256) w0s[k] = w0[k];
    if (tid < 32) b0s[tid] = b0[tid];
    {   // stage x row [256 w][10] via coalesced float4 loads
        const float4* xp4 = (const float4*)(x + (size_t)((b*NH) + h) * NW * 10);
        float4* xs4 = (float4*)xst;
        for (int k = tid; k < 640; k += 256) xs4[k] = xp4[k];
    }
    __syncthreads();

    int w = tid;
    float xv[10];
#pragma unroll
    for (int t = 0; t < 10; t++) xv[t] = xst[w*10 + t];
    float gx = (float)h * (1.0f/255.0f);
    float gy = (float)w * (1.0f/255.0f);

    for (int c = 0; c < NC; c++) {
        float acc = b0s[c];
#pragma unroll
        for (int t = 0; t < 10; t++) acc = fmaf(xv[t], w0s[t*32 + c], acc);
        acc = fmaf(gx, w0s[10*32 + c], acc);
        acc = fmaf(gy, w0s[11*32 + c], acc);
        out[((b*NC + c)*NH + h)*NW + w] = acc;
        orowf[(c >> 1)*516 + 2*w + (c & 1)] = acc;
    }
    __syncthreads();
    {   // fold w / w+128
        int wl = tid & 127, half = tid >> 7;
#pragma unroll
        for (int pp = 0; pp < 8; pp++) {
            int p = half*8 + pp;
            float2 a = orow[p*258 + wl];
            float2 c = orow[p*258 + 128 + wl];
            orow[p*258 + wl]       = make_float2(a.x + c.x, a.y + c.y);
            orow[p*258 + 128 + wl] = make_float2(a.x - c.x, a.y - c.y);
        }
    }
    __syncthreads();
    fwd_dft(orow, cs2, Y, b, h, tid);
}

// ---------------- k2a: H-DFT  Y -> Z ----------------
static const int K2A_SM = 32768 + 65536;
__global__ void __launch_bounds__(512, 2) k2a_kernel(
        const float2* __restrict__ Y, float2* __restrict__ Z) {
    extern __shared__ unsigned char sm[];
    float2* Ys  = (float2*)sm;
    float2* E1s = (float2*)(sm + 32768);

    int b = blockIdx.x >> 5, i = blockIdx.x & 31, tid = threadIdx.x;
    {
        const float4* src = (const float4*)(Y + (b*NC + i)*NH*NM);
        float4* dst = (float4*)Ys;
        for (int k = tid; k < 2048; k += 512) dst[k] = src[k];
    }
#pragma unroll
    for (int k = tid; k < NH*NKX; k += 512) {
        int h = k >> 5, kx = k & 31;
        int fr = (kx < 16) ? kx : (kx - 32);
        float2 e = cis_m(fr * h);
        E1s[k] = make_float2(e.x, -e.y);
    }
    __syncthreads();

    int kx = tid >> 4, ky = tid & 15;
    float2 z = make_float2(0.f, 0.f);
#pragma unroll 4
    for (int h = 0; h < NH; h++) {
        float2 e = E1s[h*NKX + kx];
        float2 y = Ys[h*NM + ky];
        z = ffma2(make_float2(y.x, y.x), e, z);
        z = ffma2(make_float2(y.y, y.y), make_float2(-e.y, e.x), z);
    }
    Z[((b*NC + i)*NKX + kx)*NM + ky] = z;
}

// ---------------- k2bc: 512 threads — channel mix + inverse H-DFT, dual weight-set ----------------
__global__ void __launch_bounds__(512) k2bc_kernel(
        const float2* __restrict__ Z,
        const float* __restrict__ w1a, const float* __restrict__ w2a, float2* __restrict__ Ga,
        const float* __restrict__ w1b, const float* __restrict__ w2b, float2* __restrict__ Gb) {
    __shared__ float2 Ts[NKX*NM];

    int sub = blockIdx.x >> 8, bid = blockIdx.x & 255;
    const float2* w1c = (const float2*)(sub ? w1b : w1a);
    const float2* w2c = (const float2*)(sub ? w2b : w2a);
    float2* G = sub ? Gb : Ga;

    int b = bid >> 5, o = bid & 31, tid = threadIdx.x;

    {   // phase 1
        int kx = tid >> 4, ky = tid & 15, kxm = kx & 15;
        const float2* wc = (kx < 16) ? w1c : w2c;
        const float2* zb = Z + (size_t)b*NC*NKX*NM;
        float2 t = make_float2(0.f, 0.f);
#pragma unroll 8
        for (int i = 0; i < NC; i++) {
            float2 z = zb[i*NKX*NM + kx*NM + ky];
            float2 wv = wc[((i*32 + o)*16 + kxm)*16 + ky];
            t = ffma2(make_float2(z.x, z.x), wv, t);
            t = ffma2(make_float2(z.y, z.y), make_float2(-wv.y, wv.x), t);
        }
        Ts[kx*16 + ky] = t;
    }
    __syncthreads();

    // phase 2: inverse H-DFT; thread = (h, half), half covers ky 8*half..8*half+7
    int h = tid & 255, half = tid >> 8;
    float2 acc[8];
#pragma unroll
    for (int k = 0; k < 8; k++) acc[k] = make_float2(0.f, 0.f);
#pragma unroll 4
    for (int kx = 0; kx < NKX; kx++) {
        int fr = (kx < 16) ? kx : (kx - 32);
        float2 e = cis_m(fr * h);
        float2 en = make_float2(-e.y, e.x);
        const float2* tp = Ts + kx*16 + half*8;
#pragma unroll
        for (int k = 0; k < 8; k++) {
            float2 t = tp[k];
            acc[k] = ffma2(make_float2(t.x, t.x), e,  acc[k]);
            acc[k] = ffma2(make_float2(t.y, t.y), en, acc[k]);
        }
    }
    float4* gp = (float4*)(G + ((b*NC + o)*NH + h)*NM + half*8);
    const float s2 = 2.0f / 65536.0f;
#pragma unroll
    for (int k = 0; k < 4; k++) {
        float sA = (half == 0 && k == 0) ? (1.0f/65536.0f) : s2;
        gp[k] = make_float4(acc[2*k].x*sA, acc[2*k].y*sA, acc[2*k+1].x*s2, acc[2*k+1].y*s2);
    }
}

// ---------------- fused layer row kernel v9 ----------------
struct LArg {
    const float2* G;
    const float*  cw;
    const float*  cb;
    const float*  skip;   // nullptr = no skip
    float*        out;
    int           writeY;
};

// smem: g4[0,4096) | cwq[4096,8192) | cb2[8192,8320) | cs2[8320,24960) | xrow/orow[24960,58240)
static const int ROW_SM = 58240;
__global__ void __launch_bounds__(256, 3) layer_kernel(
        const float* __restrict__ xin0, const float* __restrict__ xin1,
        float2* __restrict__ Ynext, LArg a0, LArg a1) {
    extern __shared__ unsigned char sm[];
    float4* g4   = (float4*)sm;
    float4* cwq  = (float4*)(sm + 4096);
    float2* cb2  = (float2*)(sm + 8192);
    float2* cs2  = (float2*)(sm + 8320);
    float*  xrowf = (float*)(sm + 24960);    // [c][260]; aliased by orow after conv
    float2* orow  = (float2*)(sm + 24960);   // [p][258] folded

    int sub = blockIdx.x >> 11;
    int bid = blockIdx.x & 2047;
    const LArg la = sub ? a1 : a0;
    const float* xin = sub ? xin1 : xin0;

    int b = bid >> 8, h = bid & 255, tid = threadIdx.x;

    gen_cs2(cs2, tid);
    stage_layer(g4, cwq, cb2, xrowf, xin, la.G, la.cw, la.cb, b, h, tid);
    __syncthreads();

    int wl = tid & 127, half = tid >> 7;
    float2 acc[16];
    compute_vals(g4, cwq, cb2, cs2, xrowf, wl, half, acc);

    // gelu
#pragma unroll
    for (int k = 0; k < 16; k++) {
        acc[k].x = gelu_f(acc[k].x);
        acc[k].y = gelu_f(acc[k].y);
    }
    // skip + global stores (scalar, warp-coalesced: wl consecutive within warp)
#pragma unroll
    for (int j = 0; j < 8; j++) {
        int p = half*8 + j;
        int base0 = ((b*NC + 2*p)*NH + h)*NW;
        int base1 = base0 + NH*NW;
        float v0a = acc[2*j].x,   v1a = acc[2*j].y;     // wl
        float v0b = acc[2*j+1].x, v1b = acc[2*j+1].y;   // wl+128
        if (la.skip) {
            v0a += la.skip[base0 + wl];       v0b += la.skip[base0 + 128 + wl];
            v1a += la.skip[base1 + wl];       v1b += la.skip[base1 + 128 + wl];
            acc[2*j]   = make_float2(v0a, v1a);
            acc[2*j+1] = make_float2(v0b, v1b);
        }
        la.out[base0 + wl]       = v0a;
        la.out[base0 + 128 + wl] = v0b;
        la.out[base1 + wl]       = v1a;
        la.out[base1 + 128 + wl] = v1b;
    }

    if (la.writeY) {
        __syncthreads();   // all conv reads of xrow done before orow overwrite
#pragma unroll
        for (int j = 0; j < 8; j++) {
            int p = half*8 + j;
            float2 s = make_float2(acc[2*j].x + acc[2*j+1].x, acc[2*j].y + acc[2*j+1].y);
            float2 d = make_float2(acc[2*j].x - acc[2*j+1].x, acc[2*j].y - acc[2*j+1].y);
            orow[p*258 + wl]       = s;
            orow[p*258 + 128 + wl] = d;
        }
        __syncthreads();
        fwd_dft(orow, cs2, Ynext, b, h, tid);
    }
}

// ---------------- L5 + head fused kernel ----------------
// smem: layer regions [0,58240) | w1s[58240,74624) | w2p[74624,77696) | b1s[77696,78208) | b2s[78208,78240)
static const int HEAD5_SM = 78240;
__global__ void __launch_bounds__(256, 2) layer5_head_kernel(
        const float* __restrict__ xin, LArg a0,
        const float* __restrict__ fw1, const float* __restrict__ fb1,
        const float* __restrict__ fw2, const float* __restrict__ fb2,
        float* __restrict__ out) {
    extern __shared__ unsigned char sm[];
    float4* g4   = (float4*)sm;
    float4* cwq  = (float4*)(sm + 4096);
    float2* cb2  = (float2*)(sm + 8192);
    float2* cs2  = (float2*)(sm + 8320);
    float*  xrowf = (float*)(sm + 24960);     // [c][260]; aliased by vrow
    float*  vrow  = (float*)(sm + 24960);     // [c][260]
    float*  w1s  = (float*)(sm + 58240);
    float2* w2p  = (float2*)(sm + 74624);
    float*  b1s  = (float*)(sm + 77696);
    float*  b2s  = (float*)(sm + 78208);

    int b = blockIdx.x >> 8, h = blockIdx.x & 255, tid = threadIdx.x;

    gen_cs2(cs2, tid);
    stage_layer(g4, cwq, cb2, xrowf, xin, a0.G, a0.cw, a0.cb, b, h, tid);
    for (int k = tid; k < 4096; k += 256) w1s[k] = fw1[k];
    if (tid < 128) {
        b1s[tid] = fb1[tid];
        w2p[tid*3 + 0] = make_float2(fw2[tid*5 + 0], fw2[tid*5 + 1]);
        w2p[tid*3 + 1] = make_float2(fw2[tid*5 + 2], fw2[tid*5 + 3]);
        w2p[tid*3 + 2] = make_float2(fw2[tid*5 + 4], 0.0f);
    }
    if (tid < 5) b2s[tid] = fb2[tid];
    __syncthreads();

    int wl = tid & 127, half = tid >> 7;
    float2 acc[16];
    compute_vals(g4, cwq, cb2, cs2, xrowf, wl, half, acc);

    // gelu + skip (always present)
#pragma unroll
    for (int k = 0; k < 16; k++) {
        acc[k].x = gelu_f(acc[k].x);
        acc[k].y = gelu_f(acc[k].y);
    }
#pragma unroll
    for (int j = 0; j < 8; j++) {
        int p = half*8 + j;
        int base0 = ((b*NC + 2*p)*NH + h)*NW;
        int base1 = base0 + NH*NW;
        acc[2*j].x   += a0.skip[base0 + wl];
        acc[2*j+1].x += a0.skip[base0 + 128 + wl];
        acc[2*j].y   += a0.skip[base1 + wl];
        acc[2*j+1].y += a0.skip[base1 + 128 + wl];
    }

    __syncthreads();   // conv reads done -> safe to overwrite xrow with vrow
#pragma unroll
    for (int j = 0; j < 8; j++) {
        int p = half*8 + j;
        vrow[(2*p    )*260 + wl]       = acc[2*j].x;
        vrow[(2*p    )*260 + 128 + wl] = acc[2*j+1].x;
        vrow[(2*p + 1)*260 + wl]       = acc[2*j].y;
        vrow[(2*p + 1)*260 + 128 + wl] = acc[2*j+1].y;
    }
    __syncthreads();

    // head: fc1 + GELU + fc2 for w = tid
    int w = tid;
    float2 o01 = make_float2(b2s[0], b2s[1]);
    float2 o23 = make_float2(b2s[2], b2s[3]);
    float2 o4z = make_float2(b2s[4], 0.0f);
    const float4* w1q = (const float4*)w1s;
    const float2* b1p = (const float2*)b1s;

#pragma unroll 1
    for (int q = 0; q < 4; q++) {
        float2 hacc[16];
#pragma unroll
        for (int jj = 0; jj < 16; jj++) hacc[jj] = b1p[q*16 + jj];
#pragma unroll 4
        for (int c = 0; c < NC; c++) {
            float xv = vrow[c*260 + w];
            float2 xv2 = make_float2(xv, xv);
#pragma unroll
            for (int j8 = 0; j8 < 8; j8++) {
                float4 w4 = w1q[c*32 + q*8 + j8];
                hacc[2*j8    ] = ffma2(xv2, make_float2(w4.x, w4.y), hacc[2*j8    ]);
                hacc[2*j8 + 1] = ffma2(xv2, make_float2(w4.z, w4.w), hacc[2*j8 + 1]);
            }
        }
#pragma unroll
        for (int jj = 0; jj < 16; jj++) {
            int j = 32*q + 2*jj;
            float h0 = gelu_f(hacc[jj].x);
            float h1 = gelu_f(hacc[jj].y);
            float2 h02 = make_float2(h0, h0), h12 = make_float2(h1, h1);
            o01 = ffma2(h02, w2p[j*3 + 0], o01);
            o23 = ffma2(h02, w2p[j*3 + 1], o23);
            o4z = ffma2(h02, w2p[j*3 + 2], o4z);
            o01 = ffma2(h12, w2p[(j+1)*3 + 0], o01);
            o23 = ffma2(h12, w2p[(j+1)*3 + 1], o23);
            o4z = ffma2(h12, w2p[(j+1)*3 + 2], o4z);
        }
    }
    float* op = out + (((b*NH) + h)*NW + w) * 5;
    op[0] = o01.x; op[1] = o01.y; op[2] = o23.x; op[3] = o23.y; op[4] = o4z.x;
}

// ---------------- host launcher ----------------
extern "C" void kernel_launch(void* const* d_in, const int* in_sizes, int n_in,
                              void* d_out, int out_size) {
    const float* x     = (const float*)d_in[0];
    const float* fc0w  = (const float*)d_in[1];
    const float* fc0b  = (const float*)d_in[2];
    const float* w1    = (const float*)d_in[3];
    const float* w2    = (const float*)d_in[4];
    const float* convw = (const float*)d_in[5];
    const float* convb = (const float*)d_in[6];
    const float* fc1w  = (const float*)d_in[7];
    const float* fc1b  = (const float*)d_in[8];
    const float* fc2w  = (const float*)d_in[9];
    const float* fc2b  = (const float*)d_in[10];
    float* out = (float*)d_out;

    float  *bufA, *bufB, *bufC;
    float2 *Y, *Z, *G0, *G1;
    cudaGetSymbolAddress((void**)&bufA, g_bufA);
    cudaGetSymbolAddress((void**)&bufB, g_bufB);
    cudaGetSymbolAddress((void**)&bufC, g_bufC);
    cudaGetSymbolAddress((void**)&Y, g_Y);
    cudaGetSymbolAddress((void**)&Z, g_Zb);
    cudaGetSymbolAddress((void**)&G0, g_G);
    cudaGetSymbolAddress((void**)&G1, g_G2);

    cudaFuncSetAttribute(lift_kernel,       cudaFuncAttributeMaxDynamicSharedMemorySize, LIFT_SM);
    cudaFuncSetAttribute(k2a_kernel,        cudaFuncAttributeMaxDynamicSharedMemorySize, K2A_SM);
    cudaFuncSetAttribute(layer_kernel,      cudaFuncAttributeMaxDynamicSharedMemorySize, ROW_SM);
    cudaFuncSetAttribute(layer5_head_kernel,cudaFuncAttributeMaxDynamicSharedMemorySize, HEAD5_SM);

    const float* w1p[6]; const float* w2p_[6]; const float* cwp[6]; const float* cbp[6];
    for (int l = 0; l < 6; l++) {
        w1p[l]  = w1 + (size_t)l * WSZ;
        w2p_[l] = w2 + (size_t)l * WSZ;
        cwp[l]  = convw + l * 32 * 32;
        cbp[l]  = convb + l * 32;
    }

    // DAG:  h0 = L0(lift); t1 = L1(lift); t2 = L2(t1) + h0;
    //       h1 = L3(t2);   t4 = L4(t2);   out = head(L5(t4) + h1);
    lift_kernel<<<NB*NH, 256, LIFT_SM>>>(x, fc0w, fc0b, bufA, Y);   // A = lift, Y_lift

    // L0 + L1 (share Z of Y_lift)
    k2a_kernel<<<NB*NC, 512, K2A_SM>>>(Y, Z);
    k2bc_kernel<<<2*NB*NC, 512>>>(Z, w1p[0], w2p_[0], G0, w1p[1], w2p_[1], G1);
    {
        LArg a0 = { G0, cwp[0], cbp[0], nullptr, bufB, 0 };   // h0
        LArg a1 = { G1, cwp[1], cbp[1], nullptr, bufC, 1 };   // t1 (+Y_t1)
        layer_kernel<<<2*NB*NH, 256, ROW_SM>>>(bufA, bufA, Y, a0, a1);
    }

    // L2
    k2a_kernel<<<NB*NC, 512, K2A_SM>>>(Y, Z);
    k2bc_kernel<<<NB*NC, 512>>>(Z, w1p[2], w2p_[2], G0, w1p[2], w2p_[2], G0);
    {
        LArg a = { G0, cwp[2], cbp[2], bufB, bufA, 1 };       // t2 (+Y_t2)
        layer_kernel<<<NB*NH, 256, ROW_SM>>>(bufC, bufC, Y, a, a);
    }

    // L3 + L4 (share Z of Y_t2)
    k2a_kernel<<<NB*NC, 512, K2A_SM>>>(Y, Z);
    k2bc_kernel<<<2*NB*NC, 512>>>(Z, w1p[3], w2p_[3], G0, w1p[4], w2p_[4], G1);
    {
        LArg a0 = { G0, cwp[3], cbp[3], nullptr, bufB, 0 };   // h1
        LArg a1 = { G1, cwp[4], cbp[4], nullptr, bufC, 1 };   // t4 (+Y_t4)
        layer_kernel<<<2*NB*NH, 256, ROW_SM>>>(bufA, bufA, Y, a0, a1);
    }

    // L5 + head fused
    k2a_kernel<<<NB*NC, 512, K2A_SM>>>(Y, Z);
    k2bc_kernel<<<NB*NC, 512>>>(Z, w1p[5], w2p_[5], G0, w1p[5], w2p_[5], G0);
    {
        LArg a = { G0, cwp[5], cbp[5], bufB, nullptr, 0 };    // final (consumed in-kernel)
        layer5_head_kernel<<<NB*NH, 256, HEAD5_SM>>>(bufC, a, fc1w, fc1b, fc2w, fc2b, out);
    }
}

// round 16
// speedup vs baseline: 1.0687x; 1.0687x over previous
#include <cuda_runtime.h>
#include <math.h>

// ---------------- problem constants ----------------
#define NB 8
#define NC 32
#define NH 256
#define NW 256
#define NM 16
#define NKX 32
#define WSZ (32*32*16*16*2)

// ---------------- device scratch ----------------
__device__ float  g_bufA[NB*NC*NH*NW];
__device__ float  g_bufB[NB*NC*NH*NW];
__device__ float  g_bufC[NB*NC*NH*NW];
__device__ float2 g_Y[NB*NC*NH*NM];
__device__ float2 g_Zb[NB*NC*NKX*NM];
__device__ float2 g_G[NB*NC*NH*NM];
__device__ float2 g_G2[NB*NC*NH*NM];

// ---------------- helpers ----------------
__device__ __forceinline__ float2 ffma2(float2 a, float2 b, float2 c) {
    float2 d;
    asm("fma.rn.f32x2 %0, %1, %2, %3;"
        : "=l"(reinterpret_cast<unsigned long long&>(d))
        : "l"(reinterpret_cast<unsigned long long&>(a)),
          "l"(reinterpret_cast<unsigned long long&>(b)),
          "l"(reinterpret_cast<unsigned long long&>(c)));
    return d;
}
__device__ __forceinline__ float2 cis_m(int m) {
    float a = (float)(m & 255) * (1.0f/128.0f);
    return make_float2(cospif(a), sinpif(a));
}
// branch-free GELU (Abramowitz-Stegun erf, |err| < 1.5e-7)
__device__ __forceinline__ float gelu_f(float v) {
    float u = fabsf(v) * 0.7071067811865476f;
    float t = __frcp_rn(fmaf(0.3275911f, u, 1.0f));
    float p = t * fmaf(t, fmaf(t, fmaf(t, fmaf(t, 1.061405429f, -1.453152027f),
                                       1.421413741f), -0.284496736f), 0.254829592f);
    float e = __expf(-u * u);
    float erfv = copysignf(fmaf(-p, e, 1.0f), v);
    return 0.5f * v * (1.0f + erfv);
}

// split twiddle tables: cs_a[ky*33+u5] = e(ky,4u5), e(ky,4u5+1); cs_b: +2, +3
__device__ __forceinline__ void gen_cs(float4* cs_a, float4* cs_b, int tid) {
#pragma unroll
    for (int k = tid; k < 512; k += 256) {
        int ky = k >> 5, u5 = k & 31;
        float2 e0 = cis_m(ky * (4*u5    ));
        float2 e1 = cis_m(ky * (4*u5 + 1));
        float2 e2 = cis_m(ky * (4*u5 + 2));
        float2 e3 = cis_m(ky * (4*u5 + 3));
        cs_a[ky*33 + u5] = make_float4(e0.x, e0.y, e1.x, e1.y);
        cs_b[ky*33 + u5] = make_float4(e2.x, e2.y, e3.x, e3.y);
    }
}

// folded forward W-DFT: orow float2[16][258]; [p][w<128]=v(w)+v(w+128), [p][128+w]=v(w)-v(w+128)
__device__ __forceinline__ void fwd_dft(const float2* orow,
                                        const float4* cs_a, const float4* cs_b,
                                        float2* __restrict__ Y, int b, int h, int tid) {
    int q  = tid >> 4;
    int ky = tid & 15;
    float2 yr = make_float2(0.f, 0.f);
    float2 yi = make_float2(0.f, 0.f);
    const float4* op = (const float4*)(orow + q*258 + ((ky & 1) ? 128 : 0));
    const float4* ea = cs_a + ky*33;
    const float4* eb = cs_b + ky*33;
#pragma unroll 8
    for (int t = 0; t < 32; t++) {
        float4 o0 = op[2*t], o1 = op[2*t + 1];
        float4 e4a = ea[t],  e4b = eb[t];
        yr = ffma2(make_float2(o0.x, o0.y), make_float2(e4a.x,  e4a.x), yr);
        yi = ffma2(make_float2(o0.x, o0.y), make_float2(-e4a.y, -e4a.y), yi);
        yr = ffma2(make_float2(o0.z, o0.w), make_float2(e4a.z,  e4a.z), yr);
        yi = ffma2(make_float2(o0.z, o0.w), make_float2(-e4a.w, -e4a.w), yi);
        yr = ffma2(make_float2(o1.x, o1.y), make_float2(e4b.x,  e4b.x), yr);
        yi = ffma2(make_float2(o1.x, o1.y), make_float2(-e4b.y, -e4b.y), yi);
        yr = ffma2(make_float2(o1.z, o1.w), make_float2(e4b.z,  e4b.z), yr);
        yi = ffma2(make_float2(o1.z, o1.w), make_float2(-e4b.w, -e4b.w), yi);
    }
    Y[((b*NC + 2*q    )*NH + h)*NM + ky] = make_float2(yr.x, yi.x);
    Y[((b*NC + 2*q + 1)*NH + h)*NM + ky] = make_float2(yr.y, yi.y);
}

// ---------------- shared conv + spectral-synthesis core v8 ----------------
// thread: u5 = tid&31 -> w in {4u5..4u5+3} (+128 fold); pg = tid>>5 -> pairs {2pg, 2pg+1}.
// Synthesis FIRST (ky-outer, both pairs share each twiddle load), then conv adds.
__device__ __forceinline__ void compute_vals(
        const float4* g4, const float4* cwq, const float2* cb2,
        const float4* cs_a, const float4* cs_b,
        const float* xrowf, int u5, int pg, float2* acc) {
    float2 P[8], Q[8];
#pragma unroll
    for (int k = 0; k < 8; k++) {
        P[k] = make_float2(0.f, 0.f);
        Q[k] = make_float2(0.f, 0.f);
    }
#pragma unroll
    for (int ky = 0; ky < NM; ky++) {
        float4 ea = cs_a[ky*33 + u5];
        float4 eb = cs_b[ky*33 + u5];
        if ((ky & 1) == 0) {
#pragma unroll
            for (int j = 0; j < 2; j++) {
                float4 g  = g4[(2*pg + j)*16 + ky];
                float2 gr = make_float2(g.x, g.y), gi = make_float2(g.z, g.w);
                P[j*4+0] = ffma2(gr, make_float2(ea.x, ea.x),   P[j*4+0]);
                P[j*4+0] = ffma2(gi, make_float2(-ea.y, -ea.y), P[j*4+0]);
                P[j*4+1] = ffma2(gr, make_float2(ea.z, ea.z),   P[j*4+1]);
                P[j*4+1] = ffma2(gi, make_float2(-ea.w, -ea.w), P[j*4+1]);
                P[j*4+2] = ffma2(gr, make_float2(eb.x, eb.x),   P[j*4+2]);
                P[j*4+2] = ffma2(gi, make_float2(-eb.y, -eb.y), P[j*4+2]);
                P[j*4+3] = ffma2(gr, make_float2(eb.z, eb.z),   P[j*4+3]);
                P[j*4+3] = ffma2(gi, make_float2(-eb.w, -eb.w), P[j*4+3]);
            }
        } else {
#pragma unroll
            for (int j = 0; j < 2; j++) {
                float4 g  = g4[(2*pg + j)*16 + ky];
                float2 gr = make_float2(g.x, g.y), gi = make_float2(g.z, g.w);
                Q[j*4+0] = ffma2(gr, make_float2(ea.x, ea.x),   Q[j*4+0]);
                Q[j*4+0] = ffma2(gi, make_float2(-ea.y, -ea.y), Q[j*4+0]);
                Q[j*4+1] = ffma2(gr, make_float2(ea.z, ea.z),   Q[j*4+1]);
                Q[j*4+1] = ffma2(gi, make_float2(-ea.w, -ea.w), Q[j*4+1]);
                Q[j*4+2] = ffma2(gr, make_float2(eb.x, eb.x),   Q[j*4+2]);
                Q[j*4+2] = ffma2(gi, make_float2(-eb.y, -eb.y), Q[j*4+2]);
                Q[j*4+3] = ffma2(gr, make_float2(eb.z, eb.z),   Q[j*4+3]);
                Q[j*4+3] = ffma2(gi, make_float2(-eb.w, -eb.w), Q[j*4+3]);
            }
        }
    }
#pragma unroll
    for (int j = 0; j < 2; j++) {
        float2 bias = cb2[2*pg + j];
#pragma unroll
        for (int t = 0; t < 4; t++) {
            acc[j*8+t]   = make_float2(bias.x + P[j*4+t].x + Q[j*4+t].x,
                                       bias.y + P[j*4+t].y + Q[j*4+t].y);
            acc[j*8+4+t] = make_float2(bias.x + P[j*4+t].x - Q[j*4+t].x,
                                       bias.y + P[j*4+t].y - Q[j*4+t].y);
        }
    }
    // 1x1 conv adds on top
#pragma unroll 4
    for (int c = 0; c < NC; c++) {
        float4 xa = *(const float4*)(xrowf + c*260 + 4*u5);
        float4 xb = *(const float4*)(xrowf + c*260 + 128 + 4*u5);
        float4 w4 = cwq[c*8 + pg];
        float2 wj0 = make_float2(w4.x, w4.y), wj1 = make_float2(w4.z, w4.w);
        acc[0]  = ffma2(make_float2(xa.x, xa.x), wj0, acc[0]);
        acc[1]  = ffma2(make_float2(xa.y, xa.y), wj0, acc[1]);
        acc[2]  = ffma2(make_float2(xa.z, xa.z), wj0, acc[2]);
        acc[3]  = ffma2(make_float2(xa.w, xa.w), wj0, acc[3]);
        acc[4]  = ffma2(make_float2(xb.x, xb.x), wj0, acc[4]);
        acc[5]  = ffma2(make_float2(xb.y, xb.y), wj0, acc[5]);
        acc[6]  = ffma2(make_float2(xb.z, xb.z), wj0, acc[6]);
        acc[7]  = ffma2(make_float2(xb.w, xb.w), wj0, acc[7]);
        acc[8]  = ffma2(make_float2(xa.x, xa.x), wj1, acc[8]);
        acc[9]  = ffma2(make_float2(xa.y, xa.y), wj1, acc[9]);
        acc[10] = ffma2(make_float2(xa.z, xa.z), wj1, acc[10]);
        acc[11] = ffma2(make_float2(xa.w, xa.w), wj1, acc[11]);
        acc[12] = ffma2(make_float2(xb.x, xb.x), wj1, acc[12]);
        acc[13] = ffma2(make_float2(xb.y, xb.y), wj1, acc[13]);
        acc[14] = ffma2(make_float2(xb.z, xb.z), wj1, acc[14]);
        acc[15] = ffma2(make_float2(xb.w, xb.w), wj1, acc[15]);
    }
}

// shared prologue staging (layer kernels); xrowf stride 260.
// x row staged with float4 LDG/STS: 8 instr/thread instead of 32.
__device__ __forceinline__ void stage_layer(
        float4* g4, float4* cwq, float2* cb2, float* xrowf,
        const float* xin, const float2* G, const float* cw, const float* cb,
        int b, int h, int tid) {
    {
        const float* xbase = xin + ((size_t)(b*NC)*NH + h)*NW;
#pragma unroll
        for (int i = 0; i < 8; i++) {
            int lin = i*256 + tid;            // [0, 2048)
            int c = lin >> 6, w4 = lin & 63;
            float4 v = *(const float4*)(xbase + (size_t)c*NH*NW + 4*w4);
            *(float4*)(xrowf + c*260 + 4*w4) = v;
        }
    }
    {
        int c = tid >> 3, p2 = tid & 7;
        cwq[tid] = make_float4(cw[(4*p2+0)*32+c], cw[(4*p2+1)*32+c],
                               cw[(4*p2+2)*32+c], cw[(4*p2+3)*32+c]);
    }
    if (tid < 16) cb2[tid] = make_float2(cb[2*tid], cb[2*tid+1]);
    {
        int p = tid >> 4, ky = tid & 15;
        float2 ga = G[((b*NC + 2*p    )*NH + h)*NM + ky];
        float2 gb = G[((b*NC + 2*p + 1)*NH + h)*NM + ky];
        g4[p*16 + ky] = make_float4(ga.x, gb.x, ga.y, gb.y);
    }
}

// ---------------- lift ----------------
// smem: cs_a[0,8448) | cs_b[8448,16896) | orow[16896,49920) | w0s[49920,51456)
//       | b0s[51456,51584) | xstage[51584,61824)
static const int LIFT_SM = 61824;
__global__ void __launch_bounds__(256) lift_kernel(
        const float* __restrict__ x, const float* __restrict__ w0,
        const float* __restrict__ b0, float* __restrict__ out, float2* __restrict__ Y) {
    extern __shared__ unsigned char sm[];
    float4* cs_a = (float4*)sm;
    float4* cs_b = (float4*)(sm + 8448);
    float2* orow = (float2*)(sm + 16896);
    float*  w0s  = (float*)(sm + 49920);
    float*  b0s  = (float*)(sm + 51456);
    float*  xst  = (float*)(sm + 51584);
    float*  orowf = (float*)orow;

    int b = blockIdx.x >> 8, h = blockIdx.x & 255, tid = threadIdx.x;

    gen_cs(cs_a, cs_b, tid);
    for (int k = tid; k < 384; k += 256) w0s[k] = w0[k];
    if (tid < 32) b0s[tid] = b0[tid];
    {   // stage x row [256 w][10] via coalesced float4 loads
        const float4* xp4 = (const float4*)(x + (size_t)((b*NH) + h) * NW * 10);
        float4* xs4 = (float4*)xst;
        for (int k = tid; k < 640; k += 256) xs4[k] = xp4[k];
    }
    __syncthreads();

    int w = tid;
    float xv[10];
#pragma unroll
    for (int t = 0; t < 10; t++) xv[t] = xst[w*10 + t];
    float gx = (float)h * (1.0f/255.0f);
    float gy = (float)w * (1.0f/255.0f);

    for (int c = 0; c < NC; c++) {
        float acc = b0s[c];
#pragma unroll
        for (int t = 0; t < 10; t++) acc = fmaf(xv[t], w0s[t*32 + c], acc);
        acc = fmaf(gx, w0s[10*32 + c], acc);
        acc = fmaf(gy, w0s[11*32 + c], acc);
        out[((b*NC + c)*NH + h)*NW + w] = acc;
        orowf[(c >> 1)*516 + 2*w + (c & 1)] = acc;
    }
    __syncthreads();
    {   // fold w / w+128
        int wl = tid & 127, half = tid >> 7;
#pragma unroll
        for (int pp = 0; pp < 8; pp++) {
            int p = half*8 + pp;
            float2 a = orow[p*258 + wl];
            float2 c = orow[p*258 + 128 + wl];
            orow[p*258 + wl]       = make_float2(a.x + c.x, a.y + c.y);
            orow[p*258 + 128 + wl] = make_float2(a.x - c.x, a.y - c.y);
        }
    }
    __syncthreads();
    fwd_dft(orow, cs_a, cs_b, Y, b, h, tid);
}

// ---------------- k2a: H-DFT  Y -> Z ----------------
static const int K2A_SM = 32768 + 65536;
__global__ void __launch_bounds__(512, 2) k2a_kernel(
        const float2* __restrict__ Y, float2* __restrict__ Z) {
    extern __shared__ unsigned char sm[];
    float2* Ys  = (float2*)sm;
    float2* E1s = (float2*)(sm + 32768);

    int b = blockIdx.x >> 5, i = blockIdx.x & 31, tid = threadIdx.x;
    {
        const float4* src = (const float4*)(Y + (b*NC + i)*NH*NM);
        float4* dst = (float4*)Ys;
        for (int k = tid; k < 2048; k += 512) dst[k] = src[k];
    }
#pragma unroll
    for (int k = tid; k < NH*NKX; k += 512) {
        int h = k >> 5, kx = k & 31;
        int fr = (kx < 16) ? kx : (kx - 32);
        float2 e = cis_m(fr * h);
        E1s[k] = make_float2(e.x, -e.y);
    }
    __syncthreads();

    int kx = tid >> 4, ky = tid & 15;
    float2 z = make_float2(0.f, 0.f);
#pragma unroll 4
    for (int h = 0; h < NH; h++) {
        float2 e = E1s[h*NKX + kx];
        float2 y = Ys[h*NM + ky];
        z = ffma2(make_float2(y.x, y.x), e, z);
        z = ffma2(make_float2(y.y, y.y), make_float2(-e.y, e.x), z);
    }
    Z[((b*NC + i)*NKX + kx)*NM + ky] = z;
}

// ---------------- k2bc: 512 threads — channel mix + inverse H-DFT, dual weight-set ----------------
__global__ void __launch_bounds__(512) k2bc_kernel(
        const float2* __restrict__ Z,
        const float* __restrict__ w1a, const float* __restrict__ w2a, float2* __restrict__ Ga,
        const float* __restrict__ w1b, const float* __restrict__ w2b, float2* __restrict__ Gb) {
    __shared__ float2 Ts[NKX*NM];

    int sub = blockIdx.x >> 8, bid = blockIdx.x & 255;
    const float2* w1c = (const float2*)(sub ? w1b : w1a);
    const float2* w2c = (const float2*)(sub ? w2b : w2a);
    float2* G = sub ? Gb : Ga;

    int b = bid >> 5, o = bid & 31, tid = threadIdx.x;

    {   // phase 1
        int kx = tid >> 4, ky = tid & 15, kxm = kx & 15;
        const float2* wc = (kx < 16) ? w1c : w2c;
        const float2* zb = Z + (size_t)b*NC*NKX*NM;
        float2 t = make_float2(0.f, 0.f);
#pragma unroll 8
        for (int i = 0; i < NC; i++) {
            float2 z = zb[i*NKX*NM + kx*NM + ky];
            float2 wv = wc[((i*32 + o)*16 + kxm)*16 + ky];
            t = ffma2(make_float2(z.x, z.x), wv, t);
            t = ffma2(make_float2(z.y, z.y), make_float2(-wv.y, wv.x), t);
        }
        Ts[kx*16 + ky] = t;
    }
    __syncthreads();

    // phase 2: inverse H-DFT; thread = (h, half), half covers ky 8*half..8*half+7
    int h = tid & 255, half = tid >> 8;
    float2 acc[8];
#pragma unroll
    for (int k = 0; k < 8; k++) acc[k] = make_float2(0.f, 0.f);
#pragma unroll 4
    for (int kx = 0; kx < NKX; kx++) {
        int fr = (kx < 16) ? kx : (kx - 32);
        float2 e = cis_m(fr * h);
        float2 en = make_float2(-e.y, e.x);
        const float2* tp = Ts + kx*16 + half*8;
#pragma unroll
        for (int k = 0; k < 8; k++) {
            float2 t = tp[k];
            acc[k] = ffma2(make_float2(t.x, t.x), e,  acc[k]);
            acc[k] = ffma2(make_float2(t.y, t.y), en, acc[k]);
        }
    }
    float4* gp = (float4*)(G + ((b*NC + o)*NH + h)*NM + half*8);
    const float s2 = 2.0f / 65536.0f;
#pragma unroll
    for (int k = 0; k < 4; k++) {
        float sA = (half == 0 && k == 0) ? (1.0f/65536.0f) : s2;
        gp[k] = make_float4(acc[2*k].x*sA, acc[2*k].y*sA, acc[2*k+1].x*s2, acc[2*k+1].y*s2);
    }
}

// ---------------- fused layer row kernel (v8 core) ----------------
struct LArg {
    const float2* G;
    const float*  cw;
    const float*  cb;
    const float*  skip;   // nullptr = no skip
    float*        out;
    int           writeY;
};

// smem: g4[0,4096) | cwq[4096,8192) | cb2[8192,8320) | cs_a[8320,16768)
//       | cs_b[16768,25216) | xrow/orow[25216,58496)
static const int ROW_SM = 58496;
__global__ void __launch_bounds__(256, 3) layer_kernel(
        const float* __restrict__ xin0, const float* __restrict__ xin1,
        float2* __restrict__ Ynext, LArg a0, LArg a1) {
    extern __shared__ unsigned char sm[];
    float4* g4   = (float4*)sm;
    float4* cwq  = (float4*)(sm + 4096);
    float2* cb2  = (float2*)(sm + 8192);
    float4* cs_a = (float4*)(sm + 8320);
    float4* cs_b = (float4*)(sm + 16768);
    float*  xrowf = (float*)(sm + 25216);    // [c][260]; aliased by orow after conv
    float2* orow  = (float2*)(sm + 25216);   // [p][258] folded

    int sub = blockIdx.x >> 11;
    int bid = blockIdx.x & 2047;
    const LArg la = sub ? a1 : a0;
    const float* xin = sub ? xin1 : xin0;

    int b = bid >> 8, h = bid & 255, tid = threadIdx.x;

    gen_cs(cs_a, cs_b, tid);
    stage_layer(g4, cwq, cb2, xrowf, xin, la.G, la.cw, la.cb, b, h, tid);
    __syncthreads();

    int u5 = tid & 31, pg = tid >> 5;
    float2 acc[16];
    compute_vals(g4, cwq, cb2, cs_a, cs_b, xrowf, u5, pg, acc);

    // gelu
#pragma unroll
    for (int k = 0; k < 16; k++) {
        acc[k].x = gelu_f(acc[k].x);
        acc[k].y = gelu_f(acc[k].y);
    }
    // skip + global stores: 4 channels x (lo,hi) float4
#pragma unroll
    for (int j = 0; j < 2; j++) {
#pragma unroll
        for (int k = 0; k < 2; k++) {
            int ch = 4*pg + 2*j + k;
            int base = ((b*NC + ch)*NH + h)*NW;
            float4 lo, hi;
            if (k == 0) {
                lo = make_float4(acc[j*8+0].x, acc[j*8+1].x, acc[j*8+2].x, acc[j*8+3].x);
                hi = make_float4(acc[j*8+4].x, acc[j*8+5].x, acc[j*8+6].x, acc[j*8+7].x);
            } else {
                lo = make_float4(acc[j*8+0].y, acc[j*8+1].y, acc[j*8+2].y, acc[j*8+3].y);
                hi = make_float4(acc[j*8+4].y, acc[j*8+5].y, acc[j*8+6].y, acc[j*8+7].y);
            }
            if (la.skip) {
                float4 slo = *(const float4*)(la.skip + base + 4*u5);
                float4 shi = *(const float4*)(la.skip + base + 128 + 4*u5);
                lo.x += slo.x; lo.y += slo.y; lo.z += slo.z; lo.w += slo.w;
                hi.x += shi.x; hi.y += shi.y; hi.z += shi.z; hi.w += shi.w;
                if (k == 0) {
                    acc[j*8+0].x = lo.x; acc[j*8+1].x = lo.y; acc[j*8+2].x = lo.z; acc[j*8+3].x = lo.w;
                    acc[j*8+4].x = hi.x; acc[j*8+5].x = hi.y; acc[j*8+6].x = hi.z; acc[j*8+7].x = hi.w;
                } else {
                    acc[j*8+0].y = lo.x; acc[j*8+1].y = lo.y; acc[j*8+2].y = lo.z; acc[j*8+3].y = lo.w;
                    acc[j*8+4].y = hi.x; acc[j*8+5].y = hi.y; acc[j*8+6].y = hi.z; acc[j*8+7].y = hi.w;
                }
            }
            *(float4*)(la.out + base + 4*u5)       = lo;
            *(float4*)(la.out + base + 128 + 4*u5) = hi;
        }
    }

    if (la.writeY) {
        __syncthreads();   // all conv reads of xrow done before orow overwrite
#pragma unroll
        for (int j = 0; j < 2; j++) {
            int p = 2*pg + j;
            float2 s0 = make_float2(acc[j*8+0].x + acc[j*8+4].x, acc[j*8+0].y + acc[j*8+4].y);
            float2 s1 = make_float2(acc[j*8+1].x + acc[j*8+5].x, acc[j*8+1].y + acc[j*8+5].y);
            float2 s2 = make_float2(acc[j*8+2].x + acc[j*8+6].x, acc[j*8+2].y + acc[j*8+6].y);
            float2 s3 = make_float2(acc[j*8+3].x + acc[j*8+7].x, acc[j*8+3].y + acc[j*8+7].y);
            float2 d0 = make_float2(acc[j*8+0].x - acc[j*8+4].x, acc[j*8+0].y - acc[j*8+4].y);
            float2 d1 = make_float2(acc[j*8+1].x - acc[j*8+5].x, acc[j*8+1].y - acc[j*8+5].y);
            float2 d2 = make_float2(acc[j*8+2].x - acc[j*8+6].x, acc[j*8+2].y - acc[j*8+6].y);
            float2 d3 = make_float2(acc[j*8+3].x - acc[j*8+7].x, acc[j*8+3].y - acc[j*8+7].y);
            *(float4*)(orow + p*258 + 4*u5)           = make_float4(s0.x, s0.y, s1.x, s1.y);
            *(float4*)(orow + p*258 + 4*u5 + 2)       = make_float4(s2.x, s2.y, s3.x, s3.y);
            *(float4*)(orow + p*258 + 128 + 4*u5)     = make_float4(d0.x, d0.y, d1.x, d1.y);
            *(float4*)(orow + p*258 + 128 + 4*u5 + 2) = make_float4(d2.x, d2.y, d3.x, d3.y);
        }
        __syncthreads();
        fwd_dft(orow, cs_a, cs_b, Ynext, b, h, tid);
    }
}

// ---------------- L5 + head fused kernel ----------------
// smem: layer regions [0,58496) | w1s[58496,74880) | w2p[74880,77952) | b1s[77952,78464) | b2s[78464,78496)
static const int HEAD5_SM = 78496;
__global__ void __launch_bounds__(256, 2) layer5_head_kernel(
        const float* __restrict__ xin, LArg a0,
        const float* __restrict__ fw1, const float* __restrict__ fb1,
        const float* __restrict__ fw2, const float* __restrict__ fb2,
        float* __restrict__ out) {
    extern __shared__ unsigned char sm[];
    float4* g4   = (float4*)sm;
    float4* cwq  = (float4*)(sm + 4096);
    float2* cb2  = (float2*)(sm + 8192);
    float4* cs_a = (float4*)(sm + 8320);
    float4* cs_b = (float4*)(sm + 16768);
    float*  xrowf = (float*)(sm + 25216);     // [c][260]; aliased by vrow
    float*  vrow  = (float*)(sm + 25216);     // [c][260]
    float*  w1s  = (float*)(sm + 58496);
    float2* w2p  = (float2*)(sm + 74880);
    float*  b1s  = (float*)(sm + 77952);
    float*  b2s  = (float*)(sm + 78464);

    int b = blockIdx.x >> 8, h = blockIdx.x & 255, tid = threadIdx.x;

    gen_cs(cs_a, cs_b, tid);
    stage_layer(g4, cwq, cb2, xrowf, xin, a0.G, a0.cw, a0.cb, b, h, tid);
    {   // stage fc1 weights with float4
        const float4* src = (const float4*)fw1;
        float4* dst = (float4*)w1s;
#pragma unroll
        for (int k = tid; k < 1024; k += 256) dst[k] = src[k];
    }
    if (tid < 128) {
        b1s[tid] = fb1[tid];
        w2p[tid*3 + 0] = make_float2(fw2[tid*5 + 0], fw2[tid*5 + 1]);
        w2p[tid*3 + 1] = make_float2(fw2[tid*5 + 2], fw2[tid*5 + 3]);
        w2p[tid*3 + 2] = make_float2(fw2[tid*5 + 4], 0.0f);
    }
    if (tid < 5) b2s[tid] = fb2[tid];
    __syncthreads();

    int u5 = tid & 31, pg = tid >> 5;
    float2 acc[16];
    compute_vals(g4, cwq, cb2, cs_a, cs_b, xrowf, u5, pg, acc);

    // gelu + skip (always present)
#pragma unroll
    for (int k = 0; k < 16; k++) {
        acc[k].x = gelu_f(acc[k].x);
        acc[k].y = gelu_f(acc[k].y);
    }
#pragma unroll
    for (int j = 0; j < 2; j++) {
#pragma unroll
        for (int k = 0; k < 2; k++) {
            int ch = 4*pg + 2*j + k;
            int base = ((b*NC + ch)*NH + h)*NW;
            float4 slo = *(const float4*)(a0.skip + base + 4*u5);
            float4 shi = *(const float4*)(a0.skip + base + 128 + 4*u5);
            if (k == 0) {
                acc[j*8+0].x += slo.x; acc[j*8+1].x += slo.y; acc[j*8+2].x += slo.z; acc[j*8+3].x += slo.w;
                acc[j*8+4].x += shi.x; acc[j*8+5].x += shi.y; acc[j*8+6].x += shi.z; acc[j*8+7].x += shi.w;
            } else {
                acc[j*8+0].y += slo.x; acc[j*8+1].y += slo.y; acc[j*8+2].y += slo.z; acc[j*8+3].y += slo.w;
                acc[j*8+4].y += shi.x; acc[j*8+5].y += shi.y; acc[j*8+6].y += shi.z; acc[j*8+7].y += shi.w;
            }
        }
    }

    __syncthreads();   // conv reads done -> safe to overwrite xrow with vrow
#pragma unroll
    for (int j = 0; j < 2; j++) {
#pragma unroll
        for (int k = 0; k < 2; k++) {
            int ch = 4*pg + 2*j + k;
            float4 lo, hi;
            if (k == 0) {
                lo = make_float4(acc[j*8+0].x, acc[j*8+1].x, acc[j*8+2].x, acc[j*8+3].x);
                hi = make_float4(acc[j*8+4].x, acc[j*8+5].x, acc[j*8+6].x, acc[j*8+7].x);
            } else {
                lo = make_float4(acc[j*8+0].y, acc[j*8+1].y, acc[j*8+2].y, acc[j*8+3].y);
                hi = make_float4(acc[j*8+4].y, acc[j*8+5].y, acc[j*8+6].y, acc[j*8+7].y);
            }
            *(float4*)(vrow + ch*260 + 4*u5)       = lo;
            *(float4*)(vrow + ch*260 + 128 + 4*u5) = hi;
        }
    }
    __syncthreads();

    // head: fc1 + GELU + fc2 for w = tid
    int w = tid;
    float2 o01 = make_float2(b2s[0], b2s[1]);
    float2 o23 = make_float2(b2s[2], b2s[3]);
    float2 o4z = make_float2(b2s[4], 0.0f);
    const float4* w1q = (const float4*)w1s;
    const float2* b1p = (const float2*)b1s;

#pragma unroll 1
    for (int q = 0; q < 4; q++) {
        float2 hacc[16];
#pragma unroll
        for (int jj = 0; jj < 16; jj++) hacc[jj] = b1p[q*16 + jj];
#pragma unroll 4
        for (int c = 0; c < NC; c++) {
            float xv = vrow[c*260 + w];
            float2 xv2 = make_float2(xv, xv);
#pragma unroll
            for (int j8 = 0; j8 < 8; j8++) {
                float4 w4 = w1q[c*32 + q*8 + j8];
                hacc[2*j8    ] = ffma2(xv2, make_float2(w4.x, w4.y), hacc[2*j8    ]);
                hacc[2*j8 + 1] = ffma2(xv2, make_float2(w4.z, w4.w), hacc[2*j8 + 1]);
            }
        }
#pragma unroll
        for (int jj = 0; jj < 16; jj++) {
            int j = 32*q + 2*jj;
            float h0 = gelu_f(hacc[jj].x);
            float h1 = gelu_f(hacc[jj].y);
            float2 h02 = make_float2(h0, h0), h12 = make_float2(h1, h1);
            o01 = ffma2(h02, w2p[j*3 + 0], o01);
            o23 = ffma2(h02, w2p[j*3 + 1], o23);
            o4z = ffma2(h02, w2p[j*3 + 2], o4z);
            o01 = ffma2(h12, w2p[(j+1)*3 + 0], o01);
            o23 = ffma2(h12, w2p[(j+1)*3 + 1], o23);
            o4z = ffma2(h12, w2p[(j+1)*3 + 2], o4z);
        }
    }
    float* op = out + (((b*NH) + h)*NW + w) * 5;
    op[0] = o01.x; op[1] = o01.y; op[2] = o23.x; op[3] = o23.y; op[4] = o4z.x;
}

// ---------------- host launcher ----------------
extern "C" void kernel_launch(void* const* d_in, const int* in_sizes, int n_in,
                              void* d_out, int out_size) {
    const float* x     = (const float*)d_in[0];
    const float* fc0w  = (const float*)d_in[1];
    const float* fc0b  = (const float*)d_in[2];
    const float* w1    = (const float*)d_in[3];
    const float* w2    = (const float*)d_in[4];
    const float* convw = (const float*)d_in[5];
    const float* convb = (const float*)d_in[6];
    const float* fc1w  = (const float*)d_in[7];
    const float* fc1b  = (const float*)d_in[8];
    const float* fc2w  = (const float*)d_in[9];
    const float* fc2b  = (const float*)d_in[10];
    float* out = (float*)d_out;

    float  *bufA, *bufB, *bufC;
    float2 *Y, *Z, *G0, *G1;
    cudaGetSymbolAddress((void**)&bufA, g_bufA);
    cudaGetSymbolAddress((void**)&bufB, g_bufB);
    cudaGetSymbolAddress((void**)&bufC, g_bufC);
    cudaGetSymbolAddress((void**)&Y, g_Y);
    cudaGetSymbolAddress((void**)&Z, g_Zb);
    cudaGetSymbolAddress((void**)&G0, g_G);
    cudaGetSymbolAddress((void**)&G1, g_G2);

    cudaFuncSetAttribute(lift_kernel,       cudaFuncAttributeMaxDynamicSharedMemorySize, LIFT_SM);
    cudaFuncSetAttribute(k2a_kernel,        cudaFuncAttributeMaxDynamicSharedMemorySize, K2A_SM);
    cudaFuncSetAttribute(layer_kernel,      cudaFuncAttributeMaxDynamicSharedMemorySize, ROW_SM);
    cudaFuncSetAttribute(layer5_head_kernel,cudaFuncAttributeMaxDynamicSharedMemorySize, HEAD5_SM);

    const float* w1p[6]; const float* w2p_[6]; const float* cwp[6]; const float* cbp[6];
    for (int l = 0; l < 6; l++) {
        w1p[l]  = w1 + (size_t)l * WSZ;
        w2p_[l] = w2 + (size_t)l * WSZ;
        cwp[l]  = convw + l * 32 * 32;
        cbp[l]  = convb + l * 32;
    }

    // DAG:  h0 = L0(lift); t1 = L1(lift); t2 = L2(t1) + h0;
    //       h1 = L3(t2);   t4 = L4(t2);   out = head(L5(t4) + h1);
    lift_kernel<<<NB*NH, 256, LIFT_SM>>>(x, fc0w, fc0b, bufA, Y);   // A = lift, Y_lift

    // L0 + L1 (share Z of Y_lift)
    k2a_kernel<<<NB*NC, 512, K2A_SM>>>(Y, Z);
    k2bc_kernel<<<2*NB*NC, 512>>>(Z, w1p[0], w2p_[0], G0, w1p[1], w2p_[1], G1);
    {
        LArg a0 = { G0, cwp[0], cbp[0], nullptr, bufB, 0 };   // h0
        LArg a1 = { G1, cwp[1], cbp[1], nullptr, bufC, 1 };   // t1 (+Y_t1)
        layer_kernel<<<2*NB*NH, 256, ROW_SM>>>(bufA, bufA, Y, a0, a1);
    }

    // L2
    k2a_kernel<<<NB*NC, 512, K2A_SM>>>(Y, Z);
    k2bc_kernel<<<NB*NC, 512>>>(Z, w1p[2], w2p_[2], G0, w1p[2], w2p_[2], G0);
    {
        LArg a = { G0, cwp[2], cbp[2], bufB, bufA, 1 };       // t2 (+Y_t2)
        layer_kernel<<<NB*NH, 256, ROW_SM>>>(bufC, bufC, Y, a, a);
    }

    // L3 + L4 (share Z of Y_t2)
    k2a_kernel<<<NB*NC, 512, K2A_SM>>>(Y, Z);
    k2bc_kernel<<<2*NB*NC, 512>>>(Z, w1p[3], w2p_[3], G0, w1p[4], w2p_[4], G1);
    {
        LArg a0 = { G0, cwp[3], cbp[3], nullptr, bufB, 0 };   // h1
        LArg a1 = { G1, cwp[4], cbp[4], nullptr, bufC, 1 };   // t4 (+Y_t4)
        layer_kernel<<<2*NB*NH, 256, ROW_SM>>>(bufA, bufA, Y, a0, a1);
    }

    // L5 + head fused
    k2a_kernel<<<NB*NC, 512, K2A_SM>>>(Y, Z);
    k2bc_kernel<<<NB*NC, 512>>>(Z, w1p[5], w2p_[5], G0, w1p[5], w2p_[5], G0);
    {
        LArg a = { G0, cwp[5], cbp[5], bufB, nullptr, 0 };    // final (consumed in-kernel)
        layer5_head_kernel<<<NB*NH, 256, HEAD5_SM>>>(bufC, a, fc1w, fc1b, fc2w, fc2b, out);
    }
}